// round 15
// baseline (speedup 1.0000x reference)
#include <cuda_runtime.h>
#include <cuda_bf16.h>
#include <cstdint>
#include <math_constants.h>

// Problem constants
#define B 32
#define SP 8192
#define D 2048
#define H 16
#define KVH 2
#define DH 128
#define NQKV 2560           // 2048 (q) + 256 (k) + 256 (v)
#define SCALE 0.08838834764831845f  // 1/sqrt(128)

// GEMM tiling
#define DCHUNK 256
#define NCHUNK 8            // D / DCHUNK
#define SR 32               // weight subtile rows (double-buffered)

// Attention tiling
#define TS 32               // positions per tile
#define NSTAGE 3
#define NSPLIT 32
#define SCHUNK 256          // SP / NSPLIT
#define NTILES 8            // SCHUNK / TS
#define SPST 12             // score row stride (floats)
#define TILE_BYTES (TS * DH * 4)          // 16384
#define ATTN_SMEM_BYTES ((2*NSTAGE*TS*DH + TS*SPST + 64) * 4)

// Scratch (device globals; no allocation allowed)
__device__ float g_qkv[B * NQKV];
__device__ float g_pacc[B * KVH * NSPLIT * 8 * DH];
__device__ float g_pm[B * KVH * NSPLIT * 8];
__device__ float g_pl[B * KVH * NSPLIT * 8];
__device__ float g_attn[B * H * DH];

typedef unsigned long long u64;

__device__ __forceinline__ u64 pk2(float lo, float hi) {
    u64 r;
    asm("mov.b64 %0, {%1, %2};" : "=l"(r) : "f"(lo), "f"(hi));
    return r;
}
__device__ __forceinline__ float2 upk2(u64 v) {
    float2 f;
    asm("mov.b64 {%0, %1}, %2;" : "=f"(f.x), "=f"(f.y) : "l"(v));
    return f;
}
__device__ __forceinline__ void fma2(u64& d, u64 a, u64 b) {
    asm("fma.rn.f32x2 %0, %1, %2, %0;" : "+l"(d) : "l"(a), "l"(b));
}
__device__ __forceinline__ u64 add2(u64 a, u64 b) {
    u64 r;
    asm("add.rn.f32x2 %0, %1, %2;" : "=l"(r) : "l"(a), "l"(b));
    return r;
}
__device__ __forceinline__ u64 shfl_xor64(u64 v, int m) {
    uint32_t lo = (uint32_t)v, hi = (uint32_t)(v >> 32);
    lo = __shfl_xor_sync(0xffffffffu, lo, m);
    hi = __shfl_xor_sync(0xffffffffu, hi, m);
    return ((u64)hi << 32) | (u64)lo;
}

__device__ __forceinline__ float warp_sum(float v) {
#pragma unroll
    for (int o = 16; o; o >>= 1) v += __shfl_xor_sync(0xffffffffu, v, o);
    return v;
}
__device__ __forceinline__ float warp_max(float v) {
#pragma unroll
    for (int o = 16; o; o >>= 1) v = fmaxf(v, __shfl_xor_sync(0xffffffffu, v, o));
    return v;
}

// ---- TMA / mbarrier primitives ----
#define MBAR_INIT(mbar, cnt) \
    asm volatile("mbarrier.init.shared.b64 [%0], %1;" :: "r"(mbar), "r"(cnt) : "memory")
#define MBAR_EXPECT_TX(mbar, tx) \
    asm volatile("mbarrier.arrive.expect_tx.shared.b64 _, [%0], %1;" :: "r"(mbar), "r"(tx) : "memory")
#define MBAR_WAIT(mbar, parity) do { \
    asm volatile("{\n\t.reg .pred P1;\n\t" \
        "LAB_WAIT_%=:\n\t" \
        "mbarrier.try_wait.parity.shared.b64 P1, [%0], %1;\n\t" \
        "@P1 bra LAB_DONE_%=;\n\t" \
        "bra LAB_WAIT_%=;\n\t" \
        "LAB_DONE_%=:\n\t}" \
        :: "r"(mbar), "r"(parity) : "memory"); } while (0)
#define TMA_BULK_LOAD(dst_u32, src_ptr, bytes, mbar) \
    asm volatile("cp.async.bulk.shared::cluster.global.mbarrier::complete_tx::bytes [%0], [%1], %2, [%3];" \
        :: "r"(dst_u32), "l"(src_ptr), "r"(bytes), "r"(mbar) : "memory")

// Seed g_qkv with biases (atomicAdd target for qkv_partial). grid 160, blk 512.
__global__ void qkv_seed_kernel(const float* __restrict__ bq,
                                const float* __restrict__ bk,
                                const float* __restrict__ bv)
{
    int idx = blockIdx.x * 512 + threadIdx.x;
    int c = idx % NQKV;
    float s;
    if (c < 2048) s = bq[c];
    else if (c < 2304) s = bk[c - 2048];
    else s = bv[c - 2304];
    g_qkv[idx] = s;
}

// ---------------------------------------------------------------------------
// GEMM body: weights staged in smem (cp.async double-buffered 32-row
// subtiles), X tile resident in smem. Results either stored or atomically
// accumulated (per-chunk partials -> one destination).
// ---------------------------------------------------------------------------
template <bool ATOMIC>
__device__ __forceinline__ void gemm_body(
    const float* __restrict__ Xsrc, int xld,
    const float* __restrict__ W, int Nw, int lc, int d0,
    float* __restrict__ Opart, int old_, int colbase)
{
    __shared__ float xs[DCHUNK * 33];
    __shared__ float ws[2][SR * 64];
    int t = threadIdx.x;

#pragma unroll
    for (int k2 = 0; k2 < (DCHUNK * B) / 256; k2++) {
        int idx = t + k2 * 256;
        int d = idx & (DCHUNK - 1), bb = idx / DCHUNK;
        xs[d * 33 + bb] = Xsrc[bb * xld + d0 + d];
    }

    uint32_t ws_u32 = (uint32_t)__cvta_generic_to_shared(&ws[0][0]);
    auto loadw = [&](int stage, int sub) {
        const float* src = W + (size_t)(d0 + sub * SR) * Nw + lc;
#pragma unroll
        for (int i = 0; i < 2; i++) {
            int idx = t + i * 256;
            int r = idx >> 4, c4 = idx & 15;
            asm volatile("cp.async.cg.shared.global [%0], [%1], 16;\n"
                :: "r"(ws_u32 + (stage * SR * 64 + r * 64 + c4 * 4) * 4),
                   "l"(src + (size_t)r * Nw + c4 * 4));
        }
        asm volatile("cp.async.commit_group;\n");
    };

    int cg = t & 15;   // col group (4 cols)
    int bg = t >> 4;   // batch group (2 batches)
    u64 a0 = 0, a1 = 0, a2 = 0, a3 = 0;

    loadw(0, 0);
#pragma unroll
    for (int s = 0; s < DCHUNK / SR; s++) {
        if (s + 1 < DCHUNK / SR) {
            loadw((s + 1) & 1, s + 1);
            asm volatile("cp.async.wait_group 1;\n");
        } else {
            asm volatile("cp.async.wait_group 0;\n");
        }
        __syncthreads();
        const float* wb = &ws[s & 1][0];
#pragma unroll
        for (int dd = 0; dd < SR; dd++) {
            float4 w4 = *(const float4*)(wb + dd * 64 + cg * 4);
            u64 w01 = pk2(w4.x, w4.y), w23 = pk2(w4.z, w4.w);
            float x0 = xs[(s * SR + dd) * 33 + bg * 2];
            float x1 = xs[(s * SR + dd) * 33 + bg * 2 + 1];
            u64 x00 = pk2(x0, x0), x11 = pk2(x1, x1);
            fma2(a0, x00, w01); fma2(a1, x00, w23);
            fma2(a2, x11, w01); fma2(a3, x11, w23);
        }
        __syncthreads();
    }

    float2 r0 = upk2(a0), r1 = upk2(a1), r2 = upk2(a2), r3 = upk2(a3);
    if (ATOMIC) {
        float* o0 = Opart + (size_t)(bg * 2) * old_ + colbase + cg * 4;
        float* o1 = o0 + old_;
        atomicAdd(o0 + 0, r0.x); atomicAdd(o0 + 1, r0.y);
        atomicAdd(o0 + 2, r1.x); atomicAdd(o0 + 3, r1.y);
        atomicAdd(o1 + 0, r2.x); atomicAdd(o1 + 1, r2.y);
        atomicAdd(o1 + 2, r3.x); atomicAdd(o1 + 3, r3.y);
    } else {
        float* o = Opart + ((size_t)blockIdx.y * B + bg * 2) * old_ + colbase + cg * 4;
        *(float4*)o = make_float4(r0.x, r0.y, r1.x, r1.y);
        *(float4*)(o + old_) = make_float4(r2.x, r2.y, r3.x, r3.y);
    }
}

// grid (40, 8), block 256: accumulates into bias-seeded g_qkv
__global__ __launch_bounds__(256) void qkv_partial_kernel(
    const float* __restrict__ X,
    const float* __restrict__ Wq, const float* __restrict__ Wk,
    const float* __restrict__ Wv)
{
    int colbase = blockIdx.x * 64;
    const float* W; int Nw, lc;
    if (colbase < 2048)       { W = Wq; Nw = 2048; lc = colbase; }
    else if (colbase < 2304)  { W = Wk; Nw = 256;  lc = colbase - 2048; }
    else                      { W = Wv; Nw = 256;  lc = colbase - 2304; }
    gemm_body<true>(X, D, W, Nw, lc, blockIdx.y * DCHUNK, g_qkv, NQKV, colbase);
}

// grid (32, 8), block 256: accumulates directly into out (zeroed by combine)
__global__ __launch_bounds__(256) void o_partial_kernel(const float* __restrict__ Wo,
                                                        float* __restrict__ out)
{
    int colbase = blockIdx.x * 64;
    gemm_body<true>(g_attn, D, Wo, D, colbase, blockIdx.y * DCHUNK, out, D, colbase);
}

// ---------------------------------------------------------------------------
// Split-KV flash-decode (R11 best-measured config) with INLINE RoPE on q:
// lane l holds dims l*4..l*4+3; rotate-half partner lives at lane l^16.
// K+V via TMA bulk copies, 3-stage pipeline, one __syncthreads per tile,
// no online softmax, packed f32x2 phases. grid (32,2,32), blk 256, occ 2.
// ---------------------------------------------------------------------------
__global__ __launch_bounds__(256, 2) void attn_split_kernel(
    const float* __restrict__ past_k, const float* __restrict__ past_v,
    const float* __restrict__ cosp, const float* __restrict__ sinp)
{
    extern __shared__ float sm[];
    float* k_sm = sm;                          // [NSTAGE][TS*DH]
    float* v_sm = sm + NSTAGE * TS * DH;       // [NSTAGE][TS*DH]
    float* sp   = sm + 2 * NSTAGE * TS * DH;   // [TS][SPST] probs
    float* l_sm = sp + TS * SPST;              // [8 warps][8 heads]
    __shared__ __align__(8) u64 mbars[NSTAGE];

    int split = blockIdx.x, kv = blockIdx.y, b = blockIdx.z;
    int t = threadIdx.x, w = t >> 5, l = t & 31;

    uint32_t k_u32 = (uint32_t)__cvta_generic_to_shared(k_sm);
    uint32_t v_u32 = (uint32_t)__cvta_generic_to_shared(v_sm);
    uint32_t mb_u32 = (uint32_t)__cvta_generic_to_shared(&mbars[0]);

    const float* kbase = past_k + ((size_t)(b * KVH + kv) * SP + (size_t)split * SCHUNK) * DH;
    const float* vbase = past_v + ((size_t)(b * KVH + kv) * SP + (size_t)split * SCHUNK) * DH;

    if (t == 0) {
#pragma unroll
        for (int s = 0; s < NSTAGE; s++) MBAR_INIT(mb_u32 + s * 8, 1);
    }
    __syncthreads();

    // issue loads for tiles 0..2 (one thread, 2 bulk copies each)
    if (t == 0) {
#pragma unroll
        for (int p = 0; p < NSTAGE; p++) {
            MBAR_EXPECT_TX(mb_u32 + p * 8, 2 * TILE_BYTES);
            TMA_BULK_LOAD(k_u32 + p * TILE_BYTES, kbase + (size_t)p * TS * DH,
                          TILE_BYTES, mb_u32 + p * 8);
            TMA_BULK_LOAD(v_u32 + p * TILE_BYTES, vbase + (size_t)p * TS * DH,
                          TILE_BYTES, mb_u32 + p * 8);
        }
    }

    // Load raw q, apply RoPE inline (partner dims at lane l^16), pack pairs.
    float4 c4 = *(const float4*)(cosp + b * DH + l * 4);
    float4 s4 = *(const float4*)(sinp + b * DH + l * 4);
    float sgn = (l < 16) ? -1.f : 1.f;
    float4 qr[8];
#pragma unroll
    for (int h = 0; h < 8; h++) {
        float4 q4 = *(const float4*)(g_qkv + b * NQKV + (kv * 8 + h) * DH + l * 4);
        float px = sgn * __shfl_xor_sync(0xffffffffu, q4.x, 16);
        float py = sgn * __shfl_xor_sync(0xffffffffu, q4.y, 16);
        float pz = sgn * __shfl_xor_sync(0xffffffffu, q4.z, 16);
        float pw = sgn * __shfl_xor_sync(0xffffffffu, q4.w, 16);
        qr[h].x = (q4.x * c4.x + px * s4.x) * SCALE;
        qr[h].y = (q4.y * c4.y + py * s4.y) * SCALE;
        qr[h].z = (q4.z * c4.z + pz * s4.z) * SCALE;
        qr[h].w = (q4.w * c4.w + pw * s4.w) * SCALE;
    }
    u64 q2[4][4];
#pragma unroll
    for (int p = 0; p < 4; p++) {
        q2[p][0] = pk2(qr[2 * p].x, qr[2 * p + 1].x);
        q2[p][1] = pk2(qr[2 * p].y, qr[2 * p + 1].y);
        q2[p][2] = pk2(qr[2 * p].z, qr[2 * p + 1].z);
        q2[p][3] = pk2(qr[2 * p].w, qr[2 * p + 1].w);
    }
    float l_loc = 0.f;      // on lanes 4h: running sum of probs for head h
    u64 acc[8][2] = {};

#pragma unroll
    for (int tile = 0; tile < NTILES; tile++) {
        const int stage = tile % NSTAGE;
        const uint32_t parity = (tile / NSTAGE) & 1;
        MBAR_WAIT(mb_u32 + stage * 8, parity);

        const float* kc = k_sm + stage * TS * DH;
        const float* vc = v_sm + stage * TS * DH;

        // scores: warp w -> positions w*4..w*4+3; K row read ONCE, packed
        // f32x2 dot (16 FMA2 for all 8 heads) + packed butterfly (9 SHFL).
#pragma unroll
        for (int jj = 0; jj < 4; jj++) {
            int j = w * 4 + jj;
            float4 kf = *(const float4*)(kc + j * DH + l * 4);
            u64 kx = pk2(kf.x, kf.x), ky = pk2(kf.y, kf.y);
            u64 kz = pk2(kf.z, kf.z), kw = pk2(kf.w, kf.w);
            u64 p01 = 0, p23 = 0, p45 = 0, p67 = 0;
            fma2(p01, kx, q2[0][0]); fma2(p23, kx, q2[1][0]);
            fma2(p45, kx, q2[2][0]); fma2(p67, kx, q2[3][0]);
            fma2(p01, ky, q2[0][1]); fma2(p23, ky, q2[1][1]);
            fma2(p45, ky, q2[2][1]); fma2(p67, ky, q2[3][1]);
            fma2(p01, kz, q2[0][2]); fma2(p23, kz, q2[1][2]);
            fma2(p45, kz, q2[2][2]); fma2(p67, kz, q2[3][2]);
            fma2(p01, kw, q2[0][3]); fma2(p23, kw, q2[1][3]);
            fma2(p45, kw, q2[2][3]); fma2(p67, kw, q2[3][3]);

            // xor16: keep own half's head-pairs, receive matching pairs
            u64 sendA = (l & 16) ? p01 : p45;
            u64 sendB = (l & 16) ? p23 : p67;
            u64 recvA = shfl_xor64(sendA, 16);
            u64 recvB = shfl_xor64(sendB, 16);
            u64 s0 = add2((l & 16) ? p45 : p01, recvA);
            u64 s1 = add2((l & 16) ? p67 : p23, recvB);
            // xor8
            u64 sendC = (l & 8) ? s0 : s1;
            u64 recvC = shfl_xor64(sendC, 8);
            s0 = add2((l & 8) ? s1 : s0, recvC);
            // unpack pair; xor4 resolves head = (l>>2)&7
            float2 ab = upk2(s0);
            float sendD = (l & 4) ? ab.x : ab.y;
            float recvD = __shfl_xor_sync(0xffffffffu, sendD, 4);
            float s = ((l & 4) ? ab.y : ab.x) + recvD;
            s += __shfl_xor_sync(0xffffffffu, s, 2);
            s += __shfl_xor_sync(0xffffffffu, s, 1);
            if ((l & 3) == 0) {
                float p = __expf(s);
                sp[j * SPST + (l >> 2)] = p;
                l_loc += p;
            }
        }
        __syncwarp();   // probs visible within the warp (same-warp producer)

        // V accumulation (packed): same warp reads its own positions' probs
#pragma unroll
        for (int jj = 0; jj < 4; jj++) {
            int j = w * 4 + jj;
            float4 vf = *(const float4*)(vc + j * DH + l * 4);
            u64 v01 = pk2(vf.x, vf.y), v23 = pk2(vf.z, vf.w);
            float4 pa = *(const float4*)(sp + j * SPST);
            float4 pb = *(const float4*)(sp + j * SPST + 4);
            u64 p;
            p = pk2(pa.x, pa.x); fma2(acc[0][0], p, v01); fma2(acc[0][1], p, v23);
            p = pk2(pa.y, pa.y); fma2(acc[1][0], p, v01); fma2(acc[1][1], p, v23);
            p = pk2(pa.z, pa.z); fma2(acc[2][0], p, v01); fma2(acc[2][1], p, v23);
            p = pk2(pa.w, pa.w); fma2(acc[3][0], p, v01); fma2(acc[3][1], p, v23);
            p = pk2(pb.x, pb.x); fma2(acc[4][0], p, v01); fma2(acc[4][1], p, v23);
            p = pk2(pb.y, pb.y); fma2(acc[5][0], p, v01); fma2(acc[5][1], p, v23);
            p = pk2(pb.z, pb.z); fma2(acc[6][0], p, v01); fma2(acc[6][1], p, v23);
            p = pk2(pb.w, pb.w); fma2(acc[7][0], p, v01); fma2(acc[7][1], p, v23);
        }

        // all warps done with this stage -> safe to re-arm and reload it
        __syncthreads();
        if (tile + NSTAGE < NTILES && t == 0) {
            MBAR_EXPECT_TX(mb_u32 + stage * 8, 2 * TILE_BYTES);
            TMA_BULK_LOAD(k_u32 + stage * TILE_BYTES,
                          kbase + (size_t)(tile + NSTAGE) * TS * DH,
                          TILE_BYTES, mb_u32 + stage * 8);
            TMA_BULK_LOAD(v_u32 + stage * TILE_BYTES,
                          vbase + (size_t)(tile + NSTAGE) * TS * DH,
                          TILE_BYTES, mb_u32 + stage * 8);
        }
    }

    // per-warp l partials -> smem
    if ((l & 3) == 0) l_sm[w * 8 + (l >> 2)] = l_loc;
    __syncthreads();

    // combine per-warp partial accumulators (reuse k_sm)
    float* st = k_sm;
#pragma unroll
    for (int hh = 0; hh < 8; hh++) {
        float2 x0 = upk2(acc[hh][0]), x1 = upk2(acc[hh][1]);
        *(float4*)(st + w * 1024 + hh * DH + l * 4) =
            make_float4(x0.x, x0.y, x1.x, x1.y);
    }
    __syncthreads();

    int pbase = ((b * KVH + kv) * NSPLIT + split) * 8;
#pragma unroll
    for (int it = 0; it < 4; it++) {
        int d = it * 32 + l;
        float s = 0.f;
#pragma unroll
        for (int ww = 0; ww < 8; ww++) s += st[ww * 1024 + w * DH + d];
        g_pacc[(size_t)(pbase + w) * DH + d] = s;
    }
    if (l == 0) {
        float lsum = 0.f;
#pragma unroll
        for (int ww = 0; ww < 8; ww++) lsum += l_sm[ww * 8 + w];
        g_pm[pbase + w] = 0.f;
        g_pl[pbase + w] = lsum;
    }
}

// Combine: grid (H, B), block 128. Inline RoPE on q and k_new via smem
// staging; stats via lane=split warp reduce; g_pacc prefetched in two
// register batches of 16 (MLP 16). Zeroes `out` for o_partial atomics.
__global__ __launch_bounds__(128, 8) void combine_kernel(
    float* __restrict__ out,
    const float* __restrict__ cosp, const float* __restrict__ sinp)
{
    __shared__ float red[4];
    __shared__ float qbuf[128], kbuf[128];
    int h = blockIdx.x, b = blockIdx.y;
    int t = threadIdx.x, l = t & 31;
    int kv = h >> 3, hh = h & 7;

    out[(size_t)b * D + h * 128 + t] = 0.f;   // zero for o_partial atomics

    float qraw = g_qkv[b * NQKV + h * DH + t];
    float kraw = g_qkv[b * NQKV + 2048 + kv * DH + t];
    float vn   = g_qkv[b * NQKV + 2304 + kv * DH + t];
    qbuf[t] = qraw; kbuf[t] = kraw;
    __syncthreads();

    int pd = (t + 64) & 127;
    float sgn = (t < 64) ? -1.f : 1.f;
    float cc = cosp[b * DH + t], ss = sinp[b * DH + t];
    float qd = (qraw * cc + sgn * qbuf[pd] * ss) * SCALE;
    float kn = kraw * cc + sgn * kbuf[pd] * ss;

    float ws_ = warp_sum(qd * kn);
    if (l == 0) red[t >> 5] = ws_;
    __syncthreads();
    float s_new = red[0] + red[1] + red[2] + red[3];

    int base0 = (b * KVH + kv) * NSPLIT;
    // lane = split (NSPLIT == 32)
    float m_s = g_pm[(base0 + l) * 8 + hh];
    float l_s = g_pl[(base0 + l) * 8 + hh];
    float M = fmaxf(warp_max(m_s), s_new);
    float e_s = __expf(m_s - M);
    float en = __expf(s_new - M);
    float L = warp_sum(e_s * l_s) + en;

    const float* pbase = g_pacc + (size_t)(base0 * 8 + hh) * DH + t;
    float o = en * vn;

    float pv[16];
#pragma unroll
    for (int s = 0; s < 16; s++)
        pv[s] = pbase[(size_t)s * 8 * DH];
#pragma unroll
    for (int s = 0; s < 16; s++)
        o += __shfl_sync(0xffffffffu, e_s, s) * pv[s];
#pragma unroll
    for (int s = 0; s < 16; s++)
        pv[s] = pbase[(size_t)(s + 16) * 8 * DH];
#pragma unroll
    for (int s = 0; s < 16; s++)
        o += __shfl_sync(0xffffffffu, e_s, s + 16) * pv[s];

    g_attn[b * (H * DH) + h * DH + t] = o / L;
}

extern "C" void kernel_launch(void* const* d_in, const int* in_sizes, int n_in,
                              void* d_out, int out_size)
{
    const float* hidden = (const float*)d_in[0];
    const float* cosp   = (const float*)d_in[1];
    const float* sinp   = (const float*)d_in[2];
    const float* past_k = (const float*)d_in[3];
    const float* past_v = (const float*)d_in[4];
    const float* Wq     = (const float*)d_in[5];
    const float* bq     = (const float*)d_in[6];
    const float* Wk     = (const float*)d_in[7];
    const float* bk     = (const float*)d_in[8];
    const float* Wv     = (const float*)d_in[9];
    const float* bv     = (const float*)d_in[10];
    const float* Wo     = (const float*)d_in[11];
    float* out = (float*)d_out;

    cudaFuncSetAttribute(attn_split_kernel,
                         cudaFuncAttributeMaxDynamicSharedMemorySize,
                         ATTN_SMEM_BYTES);

    qkv_seed_kernel<<<(B * NQKV) / 512, 512>>>(bq, bk, bv);
    qkv_partial_kernel<<<dim3(NQKV / 64, NCHUNK), 256>>>(hidden, Wq, Wk, Wv);
    attn_split_kernel<<<dim3(NSPLIT, KVH, B), 256, ATTN_SMEM_BYTES>>>(past_k, past_v, cosp, sinp);
    combine_kernel<<<dim3(H, B), 128>>>(out, cosp, sinp);
    o_partial_kernel<<<dim3(D / 64, NCHUNK), 256>>>(Wo, out);
}

// round 16
// speedup vs baseline: 1.0075x; 1.0075x over previous
#include <cuda_runtime.h>
#include <cuda_bf16.h>
#include <cstdint>
#include <math_constants.h>

// Problem constants
#define B 32
#define SP 8192
#define D 2048
#define H 16
#define KVH 2
#define DH 128
#define NQKV 2560           // 2048 (q) + 256 (k) + 256 (v)
#define SCALE 0.08838834764831845f  // 1/sqrt(128)

// GEMM tiling
#define DCHUNK 256
#define NCHUNK 8            // D / DCHUNK
#define SR 32               // weight subtile rows (double-buffered)

// Attention tiling
#define TS 32               // positions per tile
#define NSTAGE 3
#define NSPLIT 32
#define SCHUNK 256          // SP / NSPLIT
#define NTILES 8            // SCHUNK / TS
#define SPST 12             // score row stride (floats)
#define TILE_BYTES (TS * DH * 4)          // 16384
#define ATTN_SMEM_BYTES ((2*NSTAGE*TS*DH + TS*SPST + 64) * 4)

// Scratch (device globals; no allocation allowed)
__device__ float g_qkv_part[NCHUNK * B * NQKV];
__device__ float g_qkv[B * NQKV];
__device__ float g_pacc[B * KVH * NSPLIT * 8 * DH];
__device__ float g_pm[B * KVH * NSPLIT * 8];
__device__ float g_pl[B * KVH * NSPLIT * 8];
__device__ float g_attn[B * H * DH];

typedef unsigned long long u64;

__device__ __forceinline__ u64 pk2(float lo, float hi) {
    u64 r;
    asm("mov.b64 %0, {%1, %2};" : "=l"(r) : "f"(lo), "f"(hi));
    return r;
}
__device__ __forceinline__ float2 upk2(u64 v) {
    float2 f;
    asm("mov.b64 {%0, %1}, %2;" : "=f"(f.x), "=f"(f.y) : "l"(v));
    return f;
}
__device__ __forceinline__ void fma2(u64& d, u64 a, u64 b) {
    asm("fma.rn.f32x2 %0, %1, %2, %0;" : "+l"(d) : "l"(a), "l"(b));
}
__device__ __forceinline__ u64 add2(u64 a, u64 b) {
    u64 r;
    asm("add.rn.f32x2 %0, %1, %2;" : "=l"(r) : "l"(a), "l"(b));
    return r;
}
__device__ __forceinline__ u64 shfl_xor64(u64 v, int m) {
    uint32_t lo = (uint32_t)v, hi = (uint32_t)(v >> 32);
    lo = __shfl_xor_sync(0xffffffffu, lo, m);
    hi = __shfl_xor_sync(0xffffffffu, hi, m);
    return ((u64)hi << 32) | (u64)lo;
}

__device__ __forceinline__ float warp_sum(float v) {
#pragma unroll
    for (int o = 16; o; o >>= 1) v += __shfl_xor_sync(0xffffffffu, v, o);
    return v;
}
__device__ __forceinline__ float warp_max(float v) {
#pragma unroll
    for (int o = 16; o; o >>= 1) v = fmaxf(v, __shfl_xor_sync(0xffffffffu, v, o));
    return v;
}

// ---- TMA / mbarrier primitives ----
#define MBAR_INIT(mbar, cnt) \
    asm volatile("mbarrier.init.shared.b64 [%0], %1;" :: "r"(mbar), "r"(cnt) : "memory")
#define MBAR_EXPECT_TX(mbar, tx) \
    asm volatile("mbarrier.arrive.expect_tx.shared.b64 _, [%0], %1;" :: "r"(mbar), "r"(tx) : "memory")
#define MBAR_WAIT(mbar, parity) do { \
    asm volatile("{\n\t.reg .pred P1;\n\t" \
        "LAB_WAIT_%=:\n\t" \
        "mbarrier.try_wait.parity.shared.b64 P1, [%0], %1;\n\t" \
        "@P1 bra LAB_DONE_%=;\n\t" \
        "bra LAB_WAIT_%=;\n\t" \
        "LAB_DONE_%=:\n\t}" \
        :: "r"(mbar), "r"(parity) : "memory"); } while (0)
#define TMA_BULK_LOAD(dst_u32, src_ptr, bytes, mbar) \
    asm volatile("cp.async.bulk.shared::cluster.global.mbarrier::complete_tx::bytes [%0], [%1], %2, [%3];" \
        :: "r"(dst_u32), "l"(src_ptr), "r"(bytes), "r"(mbar) : "memory")

// ---------------------------------------------------------------------------
// GEMM body: weights staged in smem (cp.async double-buffered 32-row
// subtiles), X tile resident in smem. Results either stored (qkv) or
// atomically accumulated into out (o projection).
// ---------------------------------------------------------------------------
template <bool ATOMIC>
__device__ __forceinline__ void gemm_body(
    const float* __restrict__ Xsrc, int xld,
    const float* __restrict__ W, int Nw, int lc, int d0,
    float* __restrict__ Opart, int old_, int colbase)
{
    __shared__ float xs[DCHUNK * 33];
    __shared__ float ws[2][SR * 64];
    int t = threadIdx.x;

#pragma unroll
    for (int k2 = 0; k2 < (DCHUNK * B) / 256; k2++) {
        int idx = t + k2 * 256;
        int d = idx & (DCHUNK - 1), bb = idx / DCHUNK;
        xs[d * 33 + bb] = Xsrc[bb * xld + d0 + d];
    }

    uint32_t ws_u32 = (uint32_t)__cvta_generic_to_shared(&ws[0][0]);
    auto loadw = [&](int stage, int sub) {
        const float* src = W + (size_t)(d0 + sub * SR) * Nw + lc;
#pragma unroll
        for (int i = 0; i < 2; i++) {
            int idx = t + i * 256;
            int r = idx >> 4, c4 = idx & 15;
            asm volatile("cp.async.cg.shared.global [%0], [%1], 16;\n"
                :: "r"(ws_u32 + (stage * SR * 64 + r * 64 + c4 * 4) * 4),
                   "l"(src + (size_t)r * Nw + c4 * 4));
        }
        asm volatile("cp.async.commit_group;\n");
    };

    int cg = t & 15;   // col group (4 cols)
    int bg = t >> 4;   // batch group (2 batches)
    u64 a0 = 0, a1 = 0, a2 = 0, a3 = 0;

    loadw(0, 0);
#pragma unroll
    for (int s = 0; s < DCHUNK / SR; s++) {
        if (s + 1 < DCHUNK / SR) {
            loadw((s + 1) & 1, s + 1);
            asm volatile("cp.async.wait_group 1;\n");
        } else {
            asm volatile("cp.async.wait_group 0;\n");
        }
        __syncthreads();
        const float* wb = &ws[s & 1][0];
#pragma unroll
        for (int dd = 0; dd < SR; dd++) {
            float4 w4 = *(const float4*)(wb + dd * 64 + cg * 4);
            u64 w01 = pk2(w4.x, w4.y), w23 = pk2(w4.z, w4.w);
            float x0 = xs[(s * SR + dd) * 33 + bg * 2];
            float x1 = xs[(s * SR + dd) * 33 + bg * 2 + 1];
            u64 x00 = pk2(x0, x0), x11 = pk2(x1, x1);
            fma2(a0, x00, w01); fma2(a1, x00, w23);
            fma2(a2, x11, w01); fma2(a3, x11, w23);
        }
        __syncthreads();
    }

    float2 r0 = upk2(a0), r1 = upk2(a1), r2 = upk2(a2), r3 = upk2(a3);
    if (ATOMIC) {
        float* o0 = Opart + (size_t)(bg * 2) * old_ + colbase + cg * 4;
        float* o1 = o0 + old_;
        atomicAdd(o0 + 0, r0.x); atomicAdd(o0 + 1, r0.y);
        atomicAdd(o0 + 2, r1.x); atomicAdd(o0 + 3, r1.y);
        atomicAdd(o1 + 0, r2.x); atomicAdd(o1 + 1, r2.y);
        atomicAdd(o1 + 2, r3.x); atomicAdd(o1 + 3, r3.y);
    } else {
        float* o = Opart + ((size_t)blockIdx.y * B + bg * 2) * old_ + colbase + cg * 4;
        *(float4*)o = make_float4(r0.x, r0.y, r1.x, r1.y);
        *(float4*)(o + old_) = make_float4(r2.x, r2.y, r3.x, r3.y);
    }
}

// grid (40, 8), block 256
__global__ __launch_bounds__(256) void qkv_partial_kernel(
    const float* __restrict__ X,
    const float* __restrict__ Wq, const float* __restrict__ Wk,
    const float* __restrict__ Wv)
{
    int colbase = blockIdx.x * 64;
    const float* W; int Nw, lc;
    if (colbase < 2048)       { W = Wq; Nw = 2048; lc = colbase; }
    else if (colbase < 2304)  { W = Wk; Nw = 256;  lc = colbase - 2048; }
    else                      { W = Wv; Nw = 256;  lc = colbase - 2304; }
    gemm_body<false>(X, D, W, Nw, lc, blockIdx.y * DCHUNK, g_qkv_part, NQKV, colbase);
}

// grid (32, 8), block 256: accumulates directly into out (zeroed by combine)
__global__ __launch_bounds__(256) void o_partial_kernel(const float* __restrict__ Wo,
                                                        float* __restrict__ out)
{
    int colbase = blockIdx.x * 64;
    gemm_body<true>(g_attn, D, Wo, D, colbase, blockIdx.y * DCHUNK, out, D, colbase);
}

// Fused: reduce 8 partial chunks + bias, then RoPE. grid 160 (B*5), block 512.
__global__ void qkv_reduce_rope_kernel(const float* __restrict__ bq,
                                       const float* __restrict__ bk,
                                       const float* __restrict__ bv,
                                       const float* __restrict__ cosp,
                                       const float* __restrict__ sinp)
{
    __shared__ float buf[512];
    int b = blockIdx.x / 5, seg = blockIdx.x % 5;
    int tl = threadIdx.x;
    int c = seg * 512 + tl;

    float s;
    if (c < 2048) s = bq[c];
    else if (c < 2304) s = bk[c - 2048];
    else s = bv[c - 2304];
#pragma unroll
    for (int ch = 0; ch < NCHUNK; ch++)
        s += g_qkv_part[((size_t)ch * B + b) * NQKV + c];
    buf[tl] = s;
    __syncthreads();

    float v = s;
    if (c < 2304) {  // q or k head -> RoPE (heads are 128-aligned within segment)
        int d = c & 127;
        float xp = buf[tl - d + ((d + 64) & 127)];
        float rot = (d < 64) ? -xp : xp;
        v = v * cosp[b * DH + d] + rot * sinp[b * DH + d];
    }
    g_qkv[b * NQKV + c] = v;
}

// ---------------------------------------------------------------------------
// Split-KV flash-decode (R11/R14 best-measured config): K+V via TMA bulk
// copies (mbarrier expect_tx), 3-stage pipeline, one __syncthreads per tile,
// no online softmax, packed f32x2 phases. grid (32,2,32), blk 256, occ 2.
// ---------------------------------------------------------------------------
__global__ __launch_bounds__(256, 2) void attn_split_kernel(
    const float* __restrict__ past_k, const float* __restrict__ past_v)
{
    extern __shared__ float sm[];
    float* k_sm = sm;                          // [NSTAGE][TS*DH]
    float* v_sm = sm + NSTAGE * TS * DH;       // [NSTAGE][TS*DH]
    float* sp   = sm + 2 * NSTAGE * TS * DH;   // [TS][SPST] probs
    float* l_sm = sp + TS * SPST;              // [8 warps][8 heads]
    __shared__ __align__(8) u64 mbars[NSTAGE];

    int split = blockIdx.x, kv = blockIdx.y, b = blockIdx.z;
    int t = threadIdx.x, w = t >> 5, l = t & 31;

    uint32_t k_u32 = (uint32_t)__cvta_generic_to_shared(k_sm);
    uint32_t v_u32 = (uint32_t)__cvta_generic_to_shared(v_sm);
    uint32_t mb_u32 = (uint32_t)__cvta_generic_to_shared(&mbars[0]);

    const float* kbase = past_k + ((size_t)(b * KVH + kv) * SP + (size_t)split * SCHUNK) * DH;
    const float* vbase = past_v + ((size_t)(b * KVH + kv) * SP + (size_t)split * SCHUNK) * DH;

    if (t == 0) {
#pragma unroll
        for (int s = 0; s < NSTAGE; s++) MBAR_INIT(mb_u32 + s * 8, 1);
    }
    __syncthreads();

    // issue loads for tiles 0..2 (one thread, 2 bulk copies each)
    if (t == 0) {
#pragma unroll
        for (int p = 0; p < NSTAGE; p++) {
            MBAR_EXPECT_TX(mb_u32 + p * 8, 2 * TILE_BYTES);
            TMA_BULK_LOAD(k_u32 + p * TILE_BYTES, kbase + (size_t)p * TS * DH,
                          TILE_BYTES, mb_u32 + p * 8);
            TMA_BULK_LOAD(v_u32 + p * TILE_BYTES, vbase + (size_t)p * TS * DH,
                          TILE_BYTES, mb_u32 + p * 8);
        }
    }

    // q packed by head-pairs: q2[p][d] = (q[2p][dim], q[2p+1][dim]) * scale
    u64 q2[4][4];
#pragma unroll
    for (int p = 0; p < 4; p++) {
        float4 qa = *(const float4*)(g_qkv + b * NQKV + (kv * 8 + 2 * p) * DH + l * 4);
        float4 qb = *(const float4*)(g_qkv + b * NQKV + (kv * 8 + 2 * p + 1) * DH + l * 4);
        q2[p][0] = pk2(qa.x * SCALE, qb.x * SCALE);
        q2[p][1] = pk2(qa.y * SCALE, qb.y * SCALE);
        q2[p][2] = pk2(qa.z * SCALE, qb.z * SCALE);
        q2[p][3] = pk2(qa.w * SCALE, qb.w * SCALE);
    }
    float l_loc = 0.f;      // on lanes 4h: running sum of probs for head h
    u64 acc[8][2] = {};

#pragma unroll
    for (int tile = 0; tile < NTILES; tile++) {
        const int stage = tile % NSTAGE;
        const uint32_t parity = (tile / NSTAGE) & 1;
        MBAR_WAIT(mb_u32 + stage * 8, parity);

        const float* kc = k_sm + stage * TS * DH;
        const float* vc = v_sm + stage * TS * DH;

        // scores: warp w -> positions w*4..w*4+3; K row read ONCE, packed
        // f32x2 dot (16 FMA2 for all 8 heads) + packed butterfly (9 SHFL).
#pragma unroll
        for (int jj = 0; jj < 4; jj++) {
            int j = w * 4 + jj;
            float4 kf = *(const float4*)(kc + j * DH + l * 4);
            u64 kx = pk2(kf.x, kf.x), ky = pk2(kf.y, kf.y);
            u64 kz = pk2(kf.z, kf.z), kw = pk2(kf.w, kf.w);
            u64 p01 = 0, p23 = 0, p45 = 0, p67 = 0;
            fma2(p01, kx, q2[0][0]); fma2(p23, kx, q2[1][0]);
            fma2(p45, kx, q2[2][0]); fma2(p67, kx, q2[3][0]);
            fma2(p01, ky, q2[0][1]); fma2(p23, ky, q2[1][1]);
            fma2(p45, ky, q2[2][1]); fma2(p67, ky, q2[3][1]);
            fma2(p01, kz, q2[0][2]); fma2(p23, kz, q2[1][2]);
            fma2(p45, kz, q2[2][2]); fma2(p67, kz, q2[3][2]);
            fma2(p01, kw, q2[0][3]); fma2(p23, kw, q2[1][3]);
            fma2(p45, kw, q2[2][3]); fma2(p67, kw, q2[3][3]);

            // xor16: keep own half's head-pairs, receive matching pairs
            u64 sendA = (l & 16) ? p01 : p45;
            u64 sendB = (l & 16) ? p23 : p67;
            u64 recvA = shfl_xor64(sendA, 16);
            u64 recvB = shfl_xor64(sendB, 16);
            u64 s0 = add2((l & 16) ? p45 : p01, recvA);
            u64 s1 = add2((l & 16) ? p67 : p23, recvB);
            // xor8
            u64 sendC = (l & 8) ? s0 : s1;
            u64 recvC = shfl_xor64(sendC, 8);
            s0 = add2((l & 8) ? s1 : s0, recvC);
            // unpack pair; xor4 resolves head = (l>>2)&7
            float2 ab = upk2(s0);
            float sendD = (l & 4) ? ab.x : ab.y;
            float recvD = __shfl_xor_sync(0xffffffffu, sendD, 4);
            float s = ((l & 4) ? ab.y : ab.x) + recvD;
            s += __shfl_xor_sync(0xffffffffu, s, 2);
            s += __shfl_xor_sync(0xffffffffu, s, 1);
            if ((l & 3) == 0) {
                float p = __expf(s);
                sp[j * SPST + (l >> 2)] = p;
                l_loc += p;
            }
        }
        __syncwarp();   // probs visible within the warp (same-warp producer)

        // V accumulation (packed): same warp reads its own positions' probs
#pragma unroll
        for (int jj = 0; jj < 4; jj++) {
            int j = w * 4 + jj;
            float4 vf = *(const float4*)(vc + j * DH + l * 4);
            u64 v01 = pk2(vf.x, vf.y), v23 = pk2(vf.z, vf.w);
            float4 pa = *(const float4*)(sp + j * SPST);
            float4 pb = *(const float4*)(sp + j * SPST + 4);
            u64 p;
            p = pk2(pa.x, pa.x); fma2(acc[0][0], p, v01); fma2(acc[0][1], p, v23);
            p = pk2(pa.y, pa.y); fma2(acc[1][0], p, v01); fma2(acc[1][1], p, v23);
            p = pk2(pa.z, pa.z); fma2(acc[2][0], p, v01); fma2(acc[2][1], p, v23);
            p = pk2(pa.w, pa.w); fma2(acc[3][0], p, v01); fma2(acc[3][1], p, v23);
            p = pk2(pb.x, pb.x); fma2(acc[4][0], p, v01); fma2(acc[4][1], p, v23);
            p = pk2(pb.y, pb.y); fma2(acc[5][0], p, v01); fma2(acc[5][1], p, v23);
            p = pk2(pb.z, pb.z); fma2(acc[6][0], p, v01); fma2(acc[6][1], p, v23);
            p = pk2(pb.w, pb.w); fma2(acc[7][0], p, v01); fma2(acc[7][1], p, v23);
        }

        // all warps done with this stage -> safe to re-arm and reload it
        __syncthreads();
        if (tile + NSTAGE < NTILES && t == 0) {
            MBAR_EXPECT_TX(mb_u32 + stage * 8, 2 * TILE_BYTES);
            TMA_BULK_LOAD(k_u32 + stage * TILE_BYTES,
                          kbase + (size_t)(tile + NSTAGE) * TS * DH,
                          TILE_BYTES, mb_u32 + stage * 8);
            TMA_BULK_LOAD(v_u32 + stage * TILE_BYTES,
                          vbase + (size_t)(tile + NSTAGE) * TS * DH,
                          TILE_BYTES, mb_u32 + stage * 8);
        }
    }

    // per-warp l partials -> smem
    if ((l & 3) == 0) l_sm[w * 8 + (l >> 2)] = l_loc;
    __syncthreads();

    // combine per-warp partial accumulators (reuse k_sm)
    float* st = k_sm;
#pragma unroll
    for (int hh = 0; hh < 8; hh++) {
        float2 x0 = upk2(acc[hh][0]), x1 = upk2(acc[hh][1]);
        *(float4*)(st + w * 1024 + hh * DH + l * 4) =
            make_float4(x0.x, x0.y, x1.x, x1.y);
    }
    __syncthreads();

    int pbase = ((b * KVH + kv) * NSPLIT + split) * 8;
#pragma unroll
    for (int it = 0; it < 4; it++) {
        int d = it * 32 + l;
        float s = 0.f;
#pragma unroll
        for (int ww = 0; ww < 8; ww++) s += st[ww * 1024 + w * DH + d];
        g_pacc[(size_t)(pbase + w) * DH + d] = s;
    }
    if (l == 0) {
        float lsum = 0.f;
#pragma unroll
        for (int ww = 0; ww < 8; ww++) lsum += l_sm[ww * 8 + w];
        g_pm[pbase + w] = 0.f;
        g_pl[pbase + w] = lsum;
    }
}

// Combine: grid (H, B), block 256 = TWO split-teams (16 splits each, MLP-16
// loads in parallel across teams), merged via smem. Zeroes `out` for
// o_partial's atomic accumulation.
__global__ __launch_bounds__(256, 4) void combine_kernel(float* __restrict__ out)
{
    __shared__ float red[4];
    __shared__ float obuf[2][128];
    int h = blockIdx.x, b = blockIdx.y;
    int t = threadIdx.x, l = t & 31;
    int tm = t >> 7, d = t & 127;
    int kv = h >> 3, hh = h & 7;

    if (tm == 0) out[(size_t)b * D + h * 128 + d] = 0.f;  // zero for o_partial

    float qd = g_qkv[b * NQKV + h * DH + d] * SCALE;
    float kn = g_qkv[b * NQKV + 2048 + kv * DH + d];
    float vn = g_qkv[b * NQKV + 2304 + kv * DH + d];

    if (tm == 0) {
        float ws_ = warp_sum(qd * kn);
        if (l == 0) red[t >> 5] = ws_;
    }
    __syncthreads();
    float s_new = red[0] + red[1] + red[2] + red[3];

    int base0 = (b * KVH + kv) * NSPLIT;
    // stats computed redundantly per warp: lane = split (NSPLIT == 32)
    float m_s = g_pm[(base0 + l) * 8 + hh];
    float l_s = g_pl[(base0 + l) * 8 + hh];
    float M = fmaxf(warp_max(m_s), s_new);
    float e_s = __expf(m_s - M);
    float en = __expf(s_new - M);
    float L = warp_sum(e_s * l_s) + en;

    // team tm accumulates splits tm*16 .. tm*16+15 (16 MLP-parallel loads)
    const float* pbase = g_pacc + (size_t)((base0 + tm * 16) * 8 + hh) * DH + d;
    float pv[16];
#pragma unroll
    for (int s = 0; s < 16; s++)
        pv[s] = pbase[(size_t)s * 8 * DH];
    float o_t = 0.f;
#pragma unroll
    for (int s = 0; s < 16; s++)
        o_t += __shfl_sync(0xffffffffu, e_s, tm * 16 + s) * pv[s];

    obuf[tm][d] = o_t;
    __syncthreads();

    if (tm == 0) {
        float o = obuf[0][d] + obuf[1][d] + en * vn;
        g_attn[b * (H * DH) + h * DH + d] = o / L;
    }
}

extern "C" void kernel_launch(void* const* d_in, const int* in_sizes, int n_in,
                              void* d_out, int out_size)
{
    const float* hidden = (const float*)d_in[0];
    const float* cosp   = (const float*)d_in[1];
    const float* sinp   = (const float*)d_in[2];
    const float* past_k = (const float*)d_in[3];
    const float* past_v = (const float*)d_in[4];
    const float* Wq     = (const float*)d_in[5];
    const float* bq     = (const float*)d_in[6];
    const float* Wk     = (const float*)d_in[7];
    const float* bk     = (const float*)d_in[8];
    const float* Wv     = (const float*)d_in[9];
    const float* bv     = (const float*)d_in[10];
    const float* Wo     = (const float*)d_in[11];
    float* out = (float*)d_out;

    cudaFuncSetAttribute(attn_split_kernel,
                         cudaFuncAttributeMaxDynamicSharedMemorySize,
                         ATTN_SMEM_BYTES);

    qkv_partial_kernel<<<dim3(NQKV / 64, NCHUNK), 256>>>(hidden, Wq, Wk, Wv);
    qkv_reduce_rope_kernel<<<B * 5, 512>>>(bq, bk, bv, cosp, sinp);
    attn_split_kernel<<<dim3(NSPLIT, KVH, B), 256, ATTN_SMEM_BYTES>>>(past_k, past_v);
    combine_kernel<<<dim3(H, B), 256>>>(out);
    o_partial_kernel<<<dim3(D / 64, NCHUNK), 256>>>(Wo, out);
}

// round 17
// speedup vs baseline: 1.0108x; 1.0033x over previous
#include <cuda_runtime.h>
#include <cuda_bf16.h>
#include <cstdint>
#include <math_constants.h>

// Problem constants
#define B 32
#define SP 8192
#define D 2048
#define H 16
#define KVH 2
#define DH 128
#define NQKV 2560           // 2048 (q) + 256 (k) + 256 (v)
#define SCALE 0.08838834764831845f  // 1/sqrt(128)

// GEMM tiling
#define DCHUNK 256
#define NCHUNK 8            // D / DCHUNK
#define SR 32               // weight subtile rows (double-buffered)

// Attention tiling
#define TS 32               // positions per tile
#define NSTAGE 3
#define NSPLIT 32
#define SCHUNK 256          // SP / NSPLIT
#define NTILES 8            // SCHUNK / TS
#define SPST 12             // score row stride (floats)
#define TILE_BYTES (TS * DH * 4)          // 16384
#define ATTN_SMEM_BYTES ((2*NSTAGE*TS*DH + TS*SPST + 64) * 4)

// Scratch (device globals; no allocation allowed)
__device__ float g_qkv_part[NCHUNK * B * NQKV];
__device__ float g_qkv[B * NQKV];
__device__ float g_oacc[B * H * DH];   // plain-sum attention accumulator
__device__ float g_l[B * H];           // plain-sum softmax denominators
__device__ float g_attn[B * H * DH];

typedef unsigned long long u64;

__device__ __forceinline__ u64 pk2(float lo, float hi) {
    u64 r;
    asm("mov.b64 %0, {%1, %2};" : "=l"(r) : "f"(lo), "f"(hi));
    return r;
}
__device__ __forceinline__ float2 upk2(u64 v) {
    float2 f;
    asm("mov.b64 {%0, %1}, %2;" : "=f"(f.x), "=f"(f.y) : "l"(v));
    return f;
}
__device__ __forceinline__ void fma2(u64& d, u64 a, u64 b) {
    asm("fma.rn.f32x2 %0, %1, %2, %0;" : "+l"(d) : "l"(a), "l"(b));
}
__device__ __forceinline__ u64 add2(u64 a, u64 b) {
    u64 r;
    asm("add.rn.f32x2 %0, %1, %2;" : "=l"(r) : "l"(a), "l"(b));
    return r;
}
__device__ __forceinline__ u64 shfl_xor64(u64 v, int m) {
    uint32_t lo = (uint32_t)v, hi = (uint32_t)(v >> 32);
    lo = __shfl_xor_sync(0xffffffffu, lo, m);
    hi = __shfl_xor_sync(0xffffffffu, hi, m);
    return ((u64)hi << 32) | (u64)lo;
}

__device__ __forceinline__ float warp_sum(float v) {
#pragma unroll
    for (int o = 16; o; o >>= 1) v += __shfl_xor_sync(0xffffffffu, v, o);
    return v;
}

// ---- TMA / mbarrier primitives ----
#define MBAR_INIT(mbar, cnt) \
    asm volatile("mbarrier.init.shared.b64 [%0], %1;" :: "r"(mbar), "r"(cnt) : "memory")
#define MBAR_EXPECT_TX(mbar, tx) \
    asm volatile("mbarrier.arrive.expect_tx.shared.b64 _, [%0], %1;" :: "r"(mbar), "r"(tx) : "memory")
#define MBAR_WAIT(mbar, parity) do { \
    asm volatile("{\n\t.reg .pred P1;\n\t" \
        "LAB_WAIT_%=:\n\t" \
        "mbarrier.try_wait.parity.shared.b64 P1, [%0], %1;\n\t" \
        "@P1 bra LAB_DONE_%=;\n\t" \
        "bra LAB_WAIT_%=;\n\t" \
        "LAB_DONE_%=:\n\t}" \
        :: "r"(mbar), "r"(parity) : "memory"); } while (0)
#define TMA_BULK_LOAD(dst_u32, src_ptr, bytes, mbar) \
    asm volatile("cp.async.bulk.shared::cluster.global.mbarrier::complete_tx::bytes [%0], [%1], %2, [%3];" \
        :: "r"(dst_u32), "l"(src_ptr), "r"(bytes), "r"(mbar) : "memory")

// Zero accumulators + out. grid 128, block 512.
__global__ void seed_kernel(float* __restrict__ out)
{
    int idx = blockIdx.x * 512 + threadIdx.x;
    g_oacc[idx] = 0.f;
    out[idx] = 0.f;
    if (idx < B * H) g_l[idx] = 0.f;
}

// ---------------------------------------------------------------------------
// GEMM body: weights staged in smem (cp.async double-buffered 32-row
// subtiles), X tile resident in smem. Results either stored (qkv) or
// atomically accumulated into out (o projection).
// ---------------------------------------------------------------------------
template <bool ATOMIC>
__device__ __forceinline__ void gemm_body(
    const float* __restrict__ Xsrc, int xld,
    const float* __restrict__ W, int Nw, int lc, int d0,
    float* __restrict__ Opart, int old_, int colbase)
{
    __shared__ float xs[DCHUNK * 33];
    __shared__ float ws[2][SR * 64];
    int t = threadIdx.x;

#pragma unroll
    for (int k2 = 0; k2 < (DCHUNK * B) / 256; k2++) {
        int idx = t + k2 * 256;
        int d = idx & (DCHUNK - 1), bb = idx / DCHUNK;
        xs[d * 33 + bb] = Xsrc[bb * xld + d0 + d];
    }

    uint32_t ws_u32 = (uint32_t)__cvta_generic_to_shared(&ws[0][0]);
    auto loadw = [&](int stage, int sub) {
        const float* src = W + (size_t)(d0 + sub * SR) * Nw + lc;
#pragma unroll
        for (int i = 0; i < 2; i++) {
            int idx = t + i * 256;
            int r = idx >> 4, c4 = idx & 15;
            asm volatile("cp.async.cg.shared.global [%0], [%1], 16;\n"
                :: "r"(ws_u32 + (stage * SR * 64 + r * 64 + c4 * 4) * 4),
                   "l"(src + (size_t)r * Nw + c4 * 4));
        }
        asm volatile("cp.async.commit_group;\n");
    };

    int cg = t & 15;   // col group (4 cols)
    int bg = t >> 4;   // batch group (2 batches)
    u64 a0 = 0, a1 = 0, a2 = 0, a3 = 0;

    loadw(0, 0);
#pragma unroll
    for (int s = 0; s < DCHUNK / SR; s++) {
        if (s + 1 < DCHUNK / SR) {
            loadw((s + 1) & 1, s + 1);
            asm volatile("cp.async.wait_group 1;\n");
        } else {
            asm volatile("cp.async.wait_group 0;\n");
        }
        __syncthreads();
        const float* wb = &ws[s & 1][0];
#pragma unroll
        for (int dd = 0; dd < SR; dd++) {
            float4 w4 = *(const float4*)(wb + dd * 64 + cg * 4);
            u64 w01 = pk2(w4.x, w4.y), w23 = pk2(w4.z, w4.w);
            float x0 = xs[(s * SR + dd) * 33 + bg * 2];
            float x1 = xs[(s * SR + dd) * 33 + bg * 2 + 1];
            u64 x00 = pk2(x0, x0), x11 = pk2(x1, x1);
            fma2(a0, x00, w01); fma2(a1, x00, w23);
            fma2(a2, x11, w01); fma2(a3, x11, w23);
        }
        __syncthreads();
    }

    float2 r0 = upk2(a0), r1 = upk2(a1), r2 = upk2(a2), r3 = upk2(a3);
    if (ATOMIC) {
        float* o0 = Opart + (size_t)(bg * 2) * old_ + colbase + cg * 4;
        float* o1 = o0 + old_;
        atomicAdd(o0 + 0, r0.x); atomicAdd(o0 + 1, r0.y);
        atomicAdd(o0 + 2, r1.x); atomicAdd(o0 + 3, r1.y);
        atomicAdd(o1 + 0, r2.x); atomicAdd(o1 + 1, r2.y);
        atomicAdd(o1 + 2, r3.x); atomicAdd(o1 + 3, r3.y);
    } else {
        float* o = Opart + ((size_t)blockIdx.y * B + bg * 2) * old_ + colbase + cg * 4;
        *(float4*)o = make_float4(r0.x, r0.y, r1.x, r1.y);
        *(float4*)(o + old_) = make_float4(r2.x, r2.y, r3.x, r3.y);
    }
}

// grid (40, 8), block 256
__global__ __launch_bounds__(256) void qkv_partial_kernel(
    const float* __restrict__ X,
    const float* __restrict__ Wq, const float* __restrict__ Wk,
    const float* __restrict__ Wv)
{
    int colbase = blockIdx.x * 64;
    const float* W; int Nw, lc;
    if (colbase < 2048)       { W = Wq; Nw = 2048; lc = colbase; }
    else if (colbase < 2304)  { W = Wk; Nw = 256;  lc = colbase - 2048; }
    else                      { W = Wv; Nw = 256;  lc = colbase - 2304; }
    gemm_body<false>(X, D, W, Nw, lc, blockIdx.y * DCHUNK, g_qkv_part, NQKV, colbase);
}

// grid (32, 8), block 256: accumulates directly into out (zeroed by seed)
__global__ __launch_bounds__(256) void o_partial_kernel(const float* __restrict__ Wo,
                                                        float* __restrict__ out)
{
    int colbase = blockIdx.x * 64;
    gemm_body<true>(g_attn, D, Wo, D, colbase, blockIdx.y * DCHUNK, out, D, colbase);
}

// Fused: reduce 8 partial chunks + bias, then RoPE. grid 160 (B*5), block 512.
__global__ void qkv_reduce_rope_kernel(const float* __restrict__ bq,
                                       const float* __restrict__ bk,
                                       const float* __restrict__ bv,
                                       const float* __restrict__ cosp,
                                       const float* __restrict__ sinp)
{
    __shared__ float buf[512];
    int b = blockIdx.x / 5, seg = blockIdx.x % 5;
    int tl = threadIdx.x;
    int c = seg * 512 + tl;

    float s;
    if (c < 2048) s = bq[c];
    else if (c < 2304) s = bk[c - 2048];
    else s = bv[c - 2304];
#pragma unroll
    for (int ch = 0; ch < NCHUNK; ch++)
        s += g_qkv_part[((size_t)ch * B + b) * NQKV + c];
    buf[tl] = s;
    __syncthreads();

    float v = s;
    if (c < 2304) {  // q or k head -> RoPE (heads are 128-aligned within segment)
        int d = c & 127;
        float xp = buf[tl - d + ((d + 64) & 127)];
        float rot = (d < 64) ? -xp : xp;
        v = v * cosp[b * DH + d] + rot * sinp[b * DH + d];
    }
    g_qkv[b * NQKV + c] = v;
}

// ---------------------------------------------------------------------------
// Split-KV flash-decode (R11/R14 mainloop): K+V via TMA bulk copies, 3-stage
// pipeline, one __syncthreads per tile, no online softmax, packed f32x2
// phases. Epilogue: plain-sum atomicAdd into g_oacc / g_l (no g_pacc round
// trip — valid because all split maxima are identically 0).
// grid (32,2,32), blk 256, occ 2.
// ---------------------------------------------------------------------------
__global__ __launch_bounds__(256, 2) void attn_split_kernel(
    const float* __restrict__ past_k, const float* __restrict__ past_v)
{
    extern __shared__ float sm[];
    float* k_sm = sm;                          // [NSTAGE][TS*DH]
    float* v_sm = sm + NSTAGE * TS * DH;       // [NSTAGE][TS*DH]
    float* sp   = sm + 2 * NSTAGE * TS * DH;   // [TS][SPST] probs
    float* l_sm = sp + TS * SPST;              // [8 warps][8 heads]
    __shared__ __align__(8) u64 mbars[NSTAGE];

    int split = blockIdx.x, kv = blockIdx.y, b = blockIdx.z;
    int t = threadIdx.x, w = t >> 5, l = t & 31;

    uint32_t k_u32 = (uint32_t)__cvta_generic_to_shared(k_sm);
    uint32_t v_u32 = (uint32_t)__cvta_generic_to_shared(v_sm);
    uint32_t mb_u32 = (uint32_t)__cvta_generic_to_shared(&mbars[0]);

    const float* kbase = past_k + ((size_t)(b * KVH + kv) * SP + (size_t)split * SCHUNK) * DH;
    const float* vbase = past_v + ((size_t)(b * KVH + kv) * SP + (size_t)split * SCHUNK) * DH;

    if (t == 0) {
#pragma unroll
        for (int s = 0; s < NSTAGE; s++) MBAR_INIT(mb_u32 + s * 8, 1);
    }
    __syncthreads();

    // issue loads for tiles 0..2 (one thread, 2 bulk copies each)
    if (t == 0) {
#pragma unroll
        for (int p = 0; p < NSTAGE; p++) {
            MBAR_EXPECT_TX(mb_u32 + p * 8, 2 * TILE_BYTES);
            TMA_BULK_LOAD(k_u32 + p * TILE_BYTES, kbase + (size_t)p * TS * DH,
                          TILE_BYTES, mb_u32 + p * 8);
            TMA_BULK_LOAD(v_u32 + p * TILE_BYTES, vbase + (size_t)p * TS * DH,
                          TILE_BYTES, mb_u32 + p * 8);
        }
    }

    // q packed by head-pairs: q2[p][d] = (q[2p][dim], q[2p+1][dim]) * scale
    u64 q2[4][4];
#pragma unroll
    for (int p = 0; p < 4; p++) {
        float4 qa = *(const float4*)(g_qkv + b * NQKV + (kv * 8 + 2 * p) * DH + l * 4);
        float4 qb = *(const float4*)(g_qkv + b * NQKV + (kv * 8 + 2 * p + 1) * DH + l * 4);
        q2[p][0] = pk2(qa.x * SCALE, qb.x * SCALE);
        q2[p][1] = pk2(qa.y * SCALE, qb.y * SCALE);
        q2[p][2] = pk2(qa.z * SCALE, qb.z * SCALE);
        q2[p][3] = pk2(qa.w * SCALE, qb.w * SCALE);
    }
    float l_loc = 0.f;      // on lanes 4h: running sum of probs for head h
    u64 acc[8][2] = {};

#pragma unroll
    for (int tile = 0; tile < NTILES; tile++) {
        const int stage = tile % NSTAGE;
        const uint32_t parity = (tile / NSTAGE) & 1;
        MBAR_WAIT(mb_u32 + stage * 8, parity);

        const float* kc = k_sm + stage * TS * DH;
        const float* vc = v_sm + stage * TS * DH;

        // scores: warp w -> positions w*4..w*4+3; K row read ONCE, packed
        // f32x2 dot (16 FMA2 for all 8 heads) + packed butterfly (9 SHFL).
#pragma unroll
        for (int jj = 0; jj < 4; jj++) {
            int j = w * 4 + jj;
            float4 kf = *(const float4*)(kc + j * DH + l * 4);
            u64 kx = pk2(kf.x, kf.x), ky = pk2(kf.y, kf.y);
            u64 kz = pk2(kf.z, kf.z), kw = pk2(kf.w, kf.w);
            u64 p01 = 0, p23 = 0, p45 = 0, p67 = 0;
            fma2(p01, kx, q2[0][0]); fma2(p23, kx, q2[1][0]);
            fma2(p45, kx, q2[2][0]); fma2(p67, kx, q2[3][0]);
            fma2(p01, ky, q2[0][1]); fma2(p23, ky, q2[1][1]);
            fma2(p45, ky, q2[2][1]); fma2(p67, ky, q2[3][1]);
            fma2(p01, kz, q2[0][2]); fma2(p23, kz, q2[1][2]);
            fma2(p45, kz, q2[2][2]); fma2(p67, kz, q2[3][2]);
            fma2(p01, kw, q2[0][3]); fma2(p23, kw, q2[1][3]);
            fma2(p45, kw, q2[2][3]); fma2(p67, kw, q2[3][3]);

            // xor16: keep own half's head-pairs, receive matching pairs
            u64 sendA = (l & 16) ? p01 : p45;
            u64 sendB = (l & 16) ? p23 : p67;
            u64 recvA = shfl_xor64(sendA, 16);
            u64 recvB = shfl_xor64(sendB, 16);
            u64 s0 = add2((l & 16) ? p45 : p01, recvA);
            u64 s1 = add2((l & 16) ? p67 : p23, recvB);
            // xor8
            u64 sendC = (l & 8) ? s0 : s1;
            u64 recvC = shfl_xor64(sendC, 8);
            s0 = add2((l & 8) ? s1 : s0, recvC);
            // unpack pair; xor4 resolves head = (l>>2)&7
            float2 ab = upk2(s0);
            float sendD = (l & 4) ? ab.x : ab.y;
            float recvD = __shfl_xor_sync(0xffffffffu, sendD, 4);
            float s = ((l & 4) ? ab.y : ab.x) + recvD;
            s += __shfl_xor_sync(0xffffffffu, s, 2);
            s += __shfl_xor_sync(0xffffffffu, s, 1);
            if ((l & 3) == 0) {
                float p = __expf(s);
                sp[j * SPST + (l >> 2)] = p;
                l_loc += p;
            }
        }
        __syncwarp();   // probs visible within the warp (same-warp producer)

        // V accumulation (packed): same warp reads its own positions' probs
#pragma unroll
        for (int jj = 0; jj < 4; jj++) {
            int j = w * 4 + jj;
            float4 vf = *(const float4*)(vc + j * DH + l * 4);
            u64 v01 = pk2(vf.x, vf.y), v23 = pk2(vf.z, vf.w);
            float4 pa = *(const float4*)(sp + j * SPST);
            float4 pb = *(const float4*)(sp + j * SPST + 4);
            u64 p;
            p = pk2(pa.x, pa.x); fma2(acc[0][0], p, v01); fma2(acc[0][1], p, v23);
            p = pk2(pa.y, pa.y); fma2(acc[1][0], p, v01); fma2(acc[1][1], p, v23);
            p = pk2(pa.z, pa.z); fma2(acc[2][0], p, v01); fma2(acc[2][1], p, v23);
            p = pk2(pa.w, pa.w); fma2(acc[3][0], p, v01); fma2(acc[3][1], p, v23);
            p = pk2(pb.x, pb.x); fma2(acc[4][0], p, v01); fma2(acc[4][1], p, v23);
            p = pk2(pb.y, pb.y); fma2(acc[5][0], p, v01); fma2(acc[5][1], p, v23);
            p = pk2(pb.z, pb.z); fma2(acc[6][0], p, v01); fma2(acc[6][1], p, v23);
            p = pk2(pb.w, pb.w); fma2(acc[7][0], p, v01); fma2(acc[7][1], p, v23);
        }

        // all warps done with this stage -> safe to re-arm and reload it
        __syncthreads();
        if (tile + NSTAGE < NTILES && t == 0) {
            MBAR_EXPECT_TX(mb_u32 + stage * 8, 2 * TILE_BYTES);
            TMA_BULK_LOAD(k_u32 + stage * TILE_BYTES,
                          kbase + (size_t)(tile + NSTAGE) * TS * DH,
                          TILE_BYTES, mb_u32 + stage * 8);
            TMA_BULK_LOAD(v_u32 + stage * TILE_BYTES,
                          vbase + (size_t)(tile + NSTAGE) * TS * DH,
                          TILE_BYTES, mb_u32 + stage * 8);
        }
    }

    // per-warp l partials -> smem
    if ((l & 3) == 0) l_sm[w * 8 + (l >> 2)] = l_loc;
    __syncthreads();

    // combine per-warp partial accumulators (reuse k_sm)
    float* st = k_sm;
#pragma unroll
    for (int hh = 0; hh < 8; hh++) {
        float2 x0 = upk2(acc[hh][0]), x1 = upk2(acc[hh][1]);
        *(float4*)(st + w * 1024 + hh * DH + l * 4) =
            make_float4(x0.x, x0.y, x1.x, x1.y);
    }
    __syncthreads();

    // plain-sum epilogue: atomicAdd directly into g_oacc / g_l
    float* obase = g_oacc + b * (H * DH) + (kv * 8 + w) * DH;
#pragma unroll
    for (int it = 0; it < 4; it++) {
        int d = it * 32 + l;
        float s = 0.f;
#pragma unroll
        for (int ww = 0; ww < 8; ww++) s += st[ww * 1024 + w * DH + d];
        atomicAdd(obase + d, s);
    }
    if (l == 0) {
        float lsum = 0.f;
#pragma unroll
        for (int ww = 0; ww < 8; ww++) lsum += l_sm[ww * 8 + w];
        atomicAdd(&g_l[b * H + kv * 8 + w], lsum);
    }
}

// Finalize: fold in the NEW token and normalize. grid (H, B), block 128.
__global__ __launch_bounds__(128) void finalize_kernel()
{
    __shared__ float red[4];
    int h = blockIdx.x, b = blockIdx.y;
    int t = threadIdx.x, l = t & 31;
    int kv = h >> 3;

    float qd = g_qkv[b * NQKV + h * DH + t] * SCALE;
    float kn = g_qkv[b * NQKV + 2048 + kv * DH + t];
    float vn = g_qkv[b * NQKV + 2304 + kv * DH + t];

    float ws_ = warp_sum(qd * kn);
    if (l == 0) red[t >> 5] = ws_;
    __syncthreads();
    float s_new = red[0] + red[1] + red[2] + red[3];

    float en = __expf(s_new);
    float L = g_l[b * H + h] + en;
    float o = g_oacc[b * (H * DH) + h * DH + t] + en * vn;
    g_attn[b * (H * DH) + h * DH + t] = o / L;
}

extern "C" void kernel_launch(void* const* d_in, const int* in_sizes, int n_in,
                              void* d_out, int out_size)
{
    const float* hidden = (const float*)d_in[0];
    const float* cosp   = (const float*)d_in[1];
    const float* sinp   = (const float*)d_in[2];
    const float* past_k = (const float*)d_in[3];
    const float* past_v = (const float*)d_in[4];
    const float* Wq     = (const float*)d_in[5];
    const float* bq     = (const float*)d_in[6];
    const float* Wk     = (const float*)d_in[7];
    const float* bk     = (const float*)d_in[8];
    const float* Wv     = (const float*)d_in[9];
    const float* bv     = (const float*)d_in[10];
    const float* Wo     = (const float*)d_in[11];
    float* out = (float*)d_out;

    cudaFuncSetAttribute(attn_split_kernel,
                         cudaFuncAttributeMaxDynamicSharedMemorySize,
                         ATTN_SMEM_BYTES);

    seed_kernel<<<(B * H * DH) / 512, 512>>>(out);
    qkv_partial_kernel<<<dim3(NQKV / 64, NCHUNK), 256>>>(hidden, Wq, Wk, Wv);
    qkv_reduce_rope_kernel<<<B * 5, 512>>>(bq, bk, bv, cosp, sinp);
    attn_split_kernel<<<dim3(NSPLIT, KVH, B), 256, ATTN_SMEM_BYTES>>>(past_k, past_v);
    finalize_kernel<<<dim3(H, B), 128>>>();
    o_partial_kernel<<<dim3(D / 64, NCHUNK), 256>>>(Wo, out);
}